// round 9
// baseline (speedup 1.0000x reference)
#include <cuda_runtime.h>
#include <cstdint>

// ---------------------------------------------------------------------------
// ManifoldMatchingLoss — SINGLE fused launch with device-side phase sync.
//   Phase 1 (192 blocks): split-K Gram partials (+ exact diagonal side-channel)
//   Phase 2 (blocks 0..127): reduce row i + norms -> dist -> log_softmax -> KL
//   Phase 3 (block 128): deterministic column sum -> out; reset sync counters
// Co-residency guaranteed: __launch_bounds__(256,2) + 192 blocks <= 148*2.
// Deterministic: int-only atomics for sync; all float sums fixed-order.
// ---------------------------------------------------------------------------

#define B_N   128
#define D_F   8192          // image: 64*128
#define D_G   4096          // lang:  32*128
#define CK    64            // K-chunk per split block
#define S_F   (D_F / CK)    // 128 splits for image
#define S_G   (D_G / CK)    // 64 splits for lang
#define KSTEP 16
#define NBLK  (S_F + S_G)   // 192

__device__ float g_GfPart[S_F * B_N * B_N];   // 8 MB
__device__ float g_GgPart[S_G * B_N * B_N];   // 4 MB
__device__ float g_diagF[S_F * B_N];
__device__ float g_diagG[S_G * B_N];
__device__ float g_kl[B_N * B_N];
__device__ unsigned int g_done1;              // zero-init; reset by phase 3
__device__ unsigned int g_done2;

// ---- packed f32x2 helpers ---------------------------------------------------
__device__ __forceinline__ unsigned long long pack2(float lo, float hi) {
    unsigned long long r;
    asm("mov.b64 %0, {%1, %2};" : "=l"(r) : "f"(lo), "f"(hi));
    return r;
}
__device__ __forceinline__ float2 unpack2(unsigned long long v) {
    float2 r;
    asm("mov.b64 {%0, %1}, %2;" : "=f"(r.x), "=f"(r.y) : "l"(v));
    return r;
}
__device__ __forceinline__ void ffma2(unsigned long long& d,
                                      unsigned long long a,
                                      unsigned long long b) {
    asm("fma.rn.f32x2 %0, %1, %2, %0;" : "+l"(d) : "l"(a), "l"(b));
}

// ---- fixed-order block reduction over 256 threads (8 warps) ---------------
__device__ __forceinline__ float blkReduce256(float v, bool domax, float* sb) {
#pragma unroll
    for (int o = 16; o > 0; o >>= 1) {
        float oth = __shfl_xor_sync(0xffffffffu, v, o);
        v = domax ? fmaxf(v, oth) : (v + oth);
    }
    if ((threadIdx.x & 31) == 0) sb[threadIdx.x >> 5] = v;
    __syncthreads();
    float r;
    if (domax) r = fmaxf(fmaxf(fmaxf(sb[0], sb[1]), fmaxf(sb[2], sb[3])),
                         fmaxf(fmaxf(sb[4], sb[5]), fmaxf(sb[6], sb[7])));
    else       r = ((sb[0] + sb[1]) + (sb[2] + sb[3])) +
                   ((sb[4] + sb[5]) + (sb[6] + sb[7]));
    __syncthreads();
    return r;
}

// ---------------------------------------------------------------------------
__global__ __launch_bounds__(256, 2)
void fused_kernel(const float* __restrict__ Fm, const float* __restrict__ Gm,
                  const float* __restrict__ tptr, float* __restrict__ out) {
    __shared__ __align__(16) float As[KSTEP][132];                 // plain
    __shared__ __align__(16) unsigned long long Ad[KSTEP][133];    // (v,v) splat
    __shared__ float sC[4][2][B_N];   // gf/nf/gg/ng lo-hi combine
    __shared__ float sb[8];
    __shared__ float sNF[B_N];
    __shared__ float sNG[B_N];

    const int bx = blockIdx.x;
    const int t  = threadIdx.x;

    // =================== Phase 1: split-K Gram ===================
    {
        const float* src;
        int D, split;
        float* part;
        float* diag;
        if (bx < S_F) {
            split = bx;        src = Fm; D = D_F;
            part = g_GfPart + (size_t)split * (B_N * B_N);
            diag = g_diagF + split * B_N;
        } else {
            split = bx - S_F;  src = Gm; D = D_G;
            part = g_GgPart + (size_t)split * (B_N * B_N);
            diag = g_diagG + split * B_N;
        }
        const int k0base = split * CK;

        const int tx = t & 15;
        const int ty = t >> 4;
        const int lr = t >> 2;
        const int lq = t & 3;

        unsigned long long acc[8][4];
#pragma unroll
        for (int u = 0; u < 8; u++)
#pragma unroll
            for (int v = 0; v < 4; v++) acc[u][v] = 0ull;

        const float* p0 = src + (size_t)lr * D + k0base + lq * 4;
        const float* p1 = src + (size_t)(lr + 64) * D + k0base + lq * 4;

        float4 v0 = *(const float4*)(p0);
        float4 v1 = *(const float4*)(p1);

        for (int kc = 0; kc < CK; kc += KSTEP) {
            __syncthreads();
            {
                float a[4] = {v0.x, v0.y, v0.z, v0.w};
                float b[4] = {v1.x, v1.y, v1.z, v1.w};
#pragma unroll
                for (int q = 0; q < 4; q++) {
                    As[lq * 4 + q][lr]      = a[q];
                    As[lq * 4 + q][lr + 64] = b[q];
                    Ad[lq * 4 + q][lr]      = pack2(a[q], a[q]);
                    Ad[lq * 4 + q][lr + 64] = pack2(b[q], b[q]);
                }
            }
            __syncthreads();

            if (kc + KSTEP < CK) {
                v0 = *(const float4*)(p0 + kc + KSTEP);
                v1 = *(const float4*)(p1 + kc + KSTEP);
            }

#pragma unroll
            for (int k = 0; k < KSTEP; k++) {
                ulonglong2 lb0 = *(const ulonglong2*)&As[k][tx * 4];
                ulonglong2 lb1 = *(const ulonglong2*)&As[k][64 + tx * 4];

                unsigned long long aa[8];
#pragma unroll
                for (int u = 0; u < 4; u++) aa[u]     = Ad[k][ty * 4 + u];
#pragma unroll
                for (int u = 0; u < 4; u++) aa[4 + u] = Ad[k][64 + ty * 4 + u];

#pragma unroll
                for (int u = 0; u < 8; u++) {
                    ffma2(acc[u][0], aa[u], lb0.x);
                    ffma2(acc[u][1], aa[u], lb0.y);
                    ffma2(acc[u][2], aa[u], lb1.x);
                    ffma2(acc[u][3], aa[u], lb1.y);
                }
            }
        }

        // epilogue: coalesced float4 stores of the partial tile
#pragma unroll
        for (int u = 0; u < 8; u++) {
            int i = (u < 4) ? (ty * 4 + u) : (64 + ty * 4 + (u - 4));
            float2 c0 = unpack2(acc[u][0]);
            float2 c1 = unpack2(acc[u][1]);
            float2 c2 = unpack2(acc[u][2]);
            float2 c3 = unpack2(acc[u][3]);
            float4 w0 = make_float4(c0.x, c0.y, c1.x, c1.y);
            float4 w1 = make_float4(c2.x, c2.y, c3.x, c3.y);
            *(float4*)(part + i * B_N + tx * 4)      = w0;
            *(float4*)(part + i * B_N + 64 + tx * 4) = w1;
        }

        // diagonal side-channel: bit-identical register values to the tile
        // store -> downstream norm sums cancel the diagonal exactly.
        if (tx == ty) {
#pragma unroll
            for (int u = 0; u < 8; u++) {
                int i;
                float dval;
                if (u < 4) {
                    i = ty * 4 + u;
                    float2 p = unpack2(acc[u][u >> 1]);
                    dval = (u & 1) ? p.y : p.x;
                } else {
                    int w = u - 4;
                    i = 64 + ty * 4 + w;
                    float2 p = unpack2(acc[u][2 + (w >> 1)]);
                    dval = (w & 1) ? p.y : p.x;
                }
                diag[i] = dval;
            }
        }
    }

    // release: all threads fence, then one thread signals
    __threadfence();
    __syncthreads();
    if (t == 0) atomicAdd(&g_done1, 1u);

    // =================== Phase 2: row reduce + softmax + KL ===================
    if (bx < B_N) {
        if (t == 0) {
            while (atomicAdd(&g_done1, 0u) < NBLK) __nanosleep(64);
            __threadfence();
        }
        __syncthreads();

        const int j = t & 127;
        const int h = t >> 7;          // split half: 0 or 1
        const float eT = expf(tptr[0]);

        // NOTE: norm sums use the SAME split partition and accumulation order
        // as the gram-row sums -> for j == bx the two are bitwise equal and
        // the diagonal of sq cancels to exactly 0.
        float gf = 0.f, nf = 0.f;
        {
            const float* pr = g_GfPart + (size_t)(h * 64) * (B_N * B_N) + bx * B_N + j;
            const float* pd = g_diagF + (h * 64) * B_N + j;
#pragma unroll 16
            for (int s = 0; s < 64; s++) gf += pr[(size_t)s * (B_N * B_N)];
#pragma unroll 16
            for (int s = 0; s < 64; s++) nf += pd[s * B_N];
        }
        float gg = 0.f, ng = 0.f;
        {
            const float* pr = g_GgPart + (size_t)(h * 32) * (B_N * B_N) + bx * B_N + j;
            const float* pd = g_diagG + (h * 32) * B_N + j;
#pragma unroll 16
            for (int s = 0; s < 32; s++) gg += pr[(size_t)s * (B_N * B_N)];
#pragma unroll 16
            for (int s = 0; s < 32; s++) ng += pd[s * B_N];
        }
        sC[0][h][j] = gf;
        sC[1][h][j] = nf;
        sC[2][h][j] = gg;
        sC[3][h][j] = ng;
        __syncthreads();
        const float GF  = sC[0][0][j] + sC[0][1][j];
        const float NFj = sC[1][0][j] + sC[1][1][j];
        const float GG  = sC[2][0][j] + sC[2][1][j];
        const float NGj = sC[3][0][j] + sC[3][1][j];
        if (h == 0) { sNF[j] = NFj; sNG[j] = NGj; }
        __syncthreads();
        const float NFi = sNF[bx];
        const float NGi = sNG[bx];

        float sqf = (NFi + NFj) - 2.0f * GF;   // exactly 0 when j == bx
        float sqg = (NGi + NGj) - 2.0f * GG;
        float df = (sqf > 0.f) ? sqrtf(sqf) : 0.f;
        float dg = (sqg > 0.f) ? sqrtf(sqg) : 0.f;
        float pf = -df * eT;
        float pg = -dg * eT;

        float mf = blkReduce256(pf, true, sb);                       // max idempotent
        float sf = blkReduce256((h == 0) ? expf(pf - mf) : 0.f, false, sb);
        float mg = blkReduce256(pg, true, sb);
        float sg = blkReduce256((h == 0) ? expf(pg - mg) : 0.f, false, sb);

        if (h == 0) {
            float af = pf - (mf + logf(sf));
            float ag = pg - (mg + logf(sg));
            g_kl[bx * B_N + j] = expf(ag) * (ag - af);
        }
        __threadfence();
        __syncthreads();
        if (t == 0) atomicAdd(&g_done2, 1u);
    }
    // =================== Phase 3: column sum + counter reset ===================
    else if (bx == B_N) {
        if (t == 0) {
            while (atomicAdd(&g_done2, 0u) < (unsigned)B_N) __nanosleep(64);
            __threadfence();
        }
        __syncthreads();

        const int j = t & 127;
        const int h = t >> 7;
        float s = 0.f;
#pragma unroll 16
        for (int k = 0; k < 64; k++)
            s += g_kl[(h * 64 + k) * B_N + j];
        sC[0][h][j] = s;
        __syncthreads();
        if (h == 0) out[j] = sC[0][0][j] + sC[0][1][j];
        __syncthreads();
        if (t == 0) {               // safe: every reader of the counters is done
            g_done1 = 0u;
            g_done2 = 0u;
            __threadfence();
        }
    }
}

// ---------------------------------------------------------------------------
extern "C" void kernel_launch(void* const* d_in, const int* in_sizes, int n_in,
                              void* d_out, int out_size) {
    const float* img = nullptr;
    const float* lng = nullptr;
    const float* tmp = nullptr;
    for (int i = 0; i < n_in; i++) {
        if (in_sizes[i] == B_N * D_F)      img = (const float*)d_in[i];
        else if (in_sizes[i] == B_N * D_G) lng = (const float*)d_in[i];
        else if (in_sizes[i] == 1)         tmp = (const float*)d_in[i];
    }
    if (!img) img = (const float*)d_in[0];
    if (!lng) lng = (const float*)d_in[1];
    if (!tmp) tmp = (const float*)d_in[2];

    fused_kernel<<<NBLK, 256>>>(img, lng, tmp, (float*)d_out);
}